// round 4
// baseline (speedup 1.0000x reference)
#include <cuda_runtime.h>
#include <cuda_bf16.h>
#include <math.h>

// Problem constants
#define BATCH   16
#define HEADS   16
#define T_NEW   8
#define T_PAST  4096
#define T_FULL  4104
#define HD      64
#define CDIM    1024
#define M_ROWS  128          // B*T_new
#define QKV_N   3072

#define ATILE   128          // keys per tile in attention
#define NTILES  33           // 32*128 = 4096 past + 1 tile of 8 new

// Scratch (device globals; no allocations allowed)
__device__ float g_qkv[M_ROWS * QKV_N];   // 1.5 MB: fused QKV projection output
__device__ float g_y[M_ROWS * CDIM];      // 0.5 MB: attention output (B,T_new,C)

// ---------------------------------------------------------------------------
// fp32 GEMM: C[m][n] = sum_k A[m][k] * W[n][k] + bias[n]   (A @ W^T + b)
// BM=64, BN=64, BK=16, 256 threads, 4x4 per thread.
// mode 1: C := g_qkv (ignore Cp). mode 2: A := g_y (ignore Ap).
// ---------------------------------------------------------------------------
#define GBM 64
#define GBN 64
#define GBK 16

__global__ void __launch_bounds__(256) gemm_bias_kernel(
    const float* __restrict__ Ap, const float* __restrict__ W,
    const float* __restrict__ bias, float* __restrict__ Cp,
    int M, int N, int K, int mode)
{
    const float* A = (mode == 2) ? g_y : Ap;
    float* C = (mode == 1) ? g_qkv : Cp;

    __shared__ float a_s[GBK][GBM + 4];
    __shared__ float b_s[GBK][GBN + 4];

    const int tid = threadIdx.x;
    const int m0 = blockIdx.y * GBM;
    const int n0 = blockIdx.x * GBN;

    const int lrow = tid >> 2;   // 0..63
    const int lc4  = tid & 3;    // 0..3  -> k offset 4*lc4

    const int tx = tid & 15;     // n sub
    const int ty = tid >> 4;     // m sub

    float acc[4][4];
#pragma unroll
    for (int i = 0; i < 4; i++)
#pragma unroll
        for (int j = 0; j < 4; j++) acc[i][j] = 0.f;

    for (int k0 = 0; k0 < K; k0 += GBK) {
        {
            const float4 v = *(const float4*)&A[(size_t)(m0 + lrow) * K + k0 + 4 * lc4];
            a_s[4 * lc4 + 0][lrow] = v.x;
            a_s[4 * lc4 + 1][lrow] = v.y;
            a_s[4 * lc4 + 2][lrow] = v.z;
            a_s[4 * lc4 + 3][lrow] = v.w;
        }
        {
            const float4 v = *(const float4*)&W[(size_t)(n0 + lrow) * K + k0 + 4 * lc4];
            b_s[4 * lc4 + 0][lrow] = v.x;
            b_s[4 * lc4 + 1][lrow] = v.y;
            b_s[4 * lc4 + 2][lrow] = v.z;
            b_s[4 * lc4 + 3][lrow] = v.w;
        }
        __syncthreads();

#pragma unroll
        for (int kk = 0; kk < GBK; kk++) {
            const float4 av = *(const float4*)&a_s[kk][ty * 4];
            const float4 bv = *(const float4*)&b_s[kk][tx * 4];
            const float am[4] = {av.x, av.y, av.z, av.w};
            const float bn[4] = {bv.x, bv.y, bv.z, bv.w};
#pragma unroll
            for (int i = 0; i < 4; i++)
#pragma unroll
                for (int j = 0; j < 4; j++) acc[i][j] += am[i] * bn[j];
        }
        __syncthreads();
    }

#pragma unroll
    for (int i = 0; i < 4; i++) {
        const size_t row = (size_t)(m0 + ty * 4 + i);
#pragma unroll
        for (int j = 0; j < 4; j++) {
            const int col = n0 + tx * 4 + j;
            C[row * N + col] = acc[i][j] + bias[col];
        }
    }
}

// ---------------------------------------------------------------------------
// Fused attention + KV-cache materialization.
// Grid: 256 blocks (one per (b,h)), 256 threads (8 warps; warp w owns query w).
// Per tile of up to 128 keys:
//   - thread pair (2r, 2r+1) owns key row r: each loads 32 dims (half a row)
//     from global (past_k or g_qkv), writes them to out_k/out_v (fused copy),
//     computes partial scores for all 8 queries; pair-combined via shfl_xor(1)
//     executed WARP-UNIFORMLY (inactive threads contribute s=0).
//   - V stored TRANSPOSED into smem v_s[d][j].
//   - warp w: online softmax for query w over the tile.
//   - PV phase: warp w accumulates y[d=lane], y[d=lane+32] with lane-rotated
//     conflict-free smem reads.
// Static smem: 512 + 1024 + 8192 floats = 38 KB.
// ---------------------------------------------------------------------------
__global__ void __launch_bounds__(256) attn_fused_kernel(
    const float* __restrict__ past_k, const float* __restrict__ past_v,
    float* __restrict__ out_k, float* __restrict__ out_v)
{
    __shared__ float q_s[T_NEW * HD];        // 8*64
    __shared__ float S_s[T_NEW * ATILE];     // 8*128
    __shared__ float v_s[HD * ATILE];        // 64*128, layout [d][j]

    const int bh = blockIdx.x;
    const int b = bh >> 4;
    const int h = bh & 15;
    const int tid = threadIdx.x;
    const int lane = tid & 31;
    const int w = tid >> 5;

    const int row  = tid >> 1;   // 0..127 key row within tile
    const int half = tid & 1;    // 0/1 -> dims [half*32, half*32+32)

    // load q (scaled by 1/sqrt(hd) = 0.125)
    for (int idx = tid; idx < T_NEW * HD; idx += 256) {
        const int qi = idx >> 6, d = idx & 63;
        q_s[idx] = g_qkv[(size_t)(b * T_NEW + qi) * QKV_N + h * HD + d] * 0.125f;
    }
    __syncthreads();

    float m = -INFINITY, l = 0.f, y0 = 0.f, y1 = 0.f;
    const float4* qs4 = (const float4*)q_s;   // qs4[qi*16 + c]

    for (int t = 0; t < NTILES; t++) {
        const int nk = (t < 32) ? ATILE : T_NEW;
        const int kt = t * ATILE + row;
        const bool active = (row < nk);

        const float *kptr = nullptr, *vptr = nullptr;
        float *okp = nullptr, *ovp = nullptr;
        if (active) {
            if (kt < T_PAST) {
                kptr = past_k + ((size_t)bh * T_PAST + kt) * HD;
                vptr = past_v + ((size_t)bh * T_PAST + kt) * HD;
            } else {
                const int ni = kt - T_PAST;
                kptr = g_qkv + (size_t)(b * T_NEW + ni) * QKV_N + CDIM + h * HD;
                vptr = g_qkv + (size_t)(b * T_NEW + ni) * QKV_N + 2 * CDIM + h * HD;
            }
            okp = out_k + ((size_t)bh * T_FULL + kt) * HD;
            ovp = out_v + ((size_t)bh * T_FULL + kt) * HD;
        }

        // --- K: load 32-dim half row, fused copy-out, partial scores ---
        float s[8];
#pragma unroll
        for (int qi = 0; qi < 8; qi++) s[qi] = 0.f;
        if (active) {
            const float4* k4 = (const float4*)(kptr) + half * 8;
            float4* ok4 = (float4*)(okp) + half * 8;
#pragma unroll
            for (int c = 0; c < 8; c++) {
                const float4 kv = k4[c];
                ok4[c] = kv;
#pragma unroll
                for (int qi = 0; qi < 8; qi++) {
                    const float4 qv = qs4[qi * 16 + half * 8 + c];
                    s[qi] += qv.x * kv.x + qv.y * kv.y + qv.z * kv.z + qv.w * kv.w;
                }
            }
        }
        // pair-combine: WARP-UNIFORM (every lane of every warp executes)
#pragma unroll
        for (int qi = 0; qi < 8; qi++)
            s[qi] += __shfl_xor_sync(0xffffffffu, s[qi], 1);

        // causal mask for the 8 new keys: key T_PAST+ni visible to query qi
        // iff ni <= qi
        if (active && kt >= T_PAST) {
            const int ni = kt - T_PAST;
#pragma unroll
            for (int qi = 0; qi < 8; qi++)
                if (qi < ni) s[qi] = -INFINITY;
        }
        if (half == 0) {
#pragma unroll
            for (int qi = 0; qi < 8; qi++)
                S_s[qi * ATILE + row] = active ? s[qi] : -INFINITY;
        }

        // --- V: load half row, fused copy-out, transposed smem store ---
        if (active) {
            const float4* v4 = (const float4*)(vptr) + half * 8;
            float4* ov4 = (float4*)(ovp) + half * 8;
#pragma unroll
            for (int c = 0; c < 8; c++) {
                const float4 vv = v4[c];
                ov4[c] = vv;
                const int d = half * 32 + c * 4;
                v_s[(d + 0) * ATILE + row] = vv.x;
                v_s[(d + 1) * ATILE + row] = vv.y;
                v_s[(d + 2) * ATILE + row] = vv.z;
                v_s[(d + 3) * ATILE + row] = vv.w;
            }
        }
        __syncthreads();

        // --- online softmax: warp w owns query w (block-uniform code) ---
        float pr[4];
        float lmax = -INFINITY;
#pragma unroll
        for (int k = 0; k < 4; k++) {
            pr[k] = S_s[w * ATILE + lane + 32 * k];
            lmax = fmaxf(lmax, pr[k]);
        }
#pragma unroll
        for (int off = 16; off; off >>= 1)
            lmax = fmaxf(lmax, __shfl_xor_sync(0xffffffffu, lmax, off));
        const float m_new = fmaxf(m, lmax);
        const float factor = __expf(m - m_new);
        float psum = 0.f;
#pragma unroll
        for (int k = 0; k < 4; k++) {
            const float e = __expf(pr[k] - m_new);
            psum += e;
            S_s[w * ATILE + lane + 32 * k] = e;
        }
#pragma unroll
        for (int off = 16; off; off >>= 1)
            psum += __shfl_xor_sync(0xffffffffu, psum, off);
        l = l * factor + psum;
        y0 *= factor;
        y1 *= factor;
        m = m_new;
        __syncwarp();

        // --- PV accumulate: lane-rotated conflict-free reads ---
#pragma unroll 8
        for (int j = 0; j < ATILE; j++) {
            const int je = (j + lane) & (ATILE - 1);
            const float pv = S_s[w * ATILE + je];
            y0 += pv * v_s[lane * ATILE + je];
            y1 += pv * v_s[(lane + 32) * ATILE + je];
        }
        __syncthreads();   // protect S_s / v_s before next tile overwrites
    }

    const float inv = 1.f / l;
    const size_t yb = (size_t)(b * T_NEW + w) * CDIM + h * HD;
    g_y[yb + lane] = y0 * inv;
    g_y[yb + lane + 32] = y1 * inv;
}

// ---------------------------------------------------------------------------
// Launcher — ONLY kernel launches, no other CUDA API calls.
// Inputs: 0:x 1:past_k 2:past_v 3:W_attn 4:b_attn 5:W_proj 6:b_proj
// Output layout: [ out (128*1024) | k (256*4104*64) | v (256*4104*64) ]
// ---------------------------------------------------------------------------
extern "C" void kernel_launch(void* const* d_in, const int* in_sizes, int n_in,
                              void* d_out, int out_size)
{
    const float* x      = (const float*)d_in[0];
    const float* past_k = (const float*)d_in[1];
    const float* past_v = (const float*)d_in[2];
    const float* W_attn = (const float*)d_in[3];
    const float* b_attn = (const float*)d_in[4];
    const float* W_proj = (const float*)d_in[5];
    const float* b_proj = (const float*)d_in[6];

    float* out   = (float*)d_out;
    float* out_k = out + (size_t)M_ROWS * CDIM;
    float* out_v = out_k + (size_t)BATCH * HEADS * T_FULL * HD;

    // 1) QKV projection: (128 x 1024) @ (3072 x 1024)^T + b -> g_qkv
    {
        dim3 grid(QKV_N / GBN, M_ROWS / GBM);
        gemm_bias_kernel<<<grid, 256>>>(x, W_attn, b_attn, nullptr,
                                        M_ROWS, QKV_N, CDIM, 1);
    }

    // 2) Fused attention + KV-cache copy
    attn_fused_kernel<<<BATCH * HEADS, 256>>>(past_k, past_v, out_k, out_v);

    // 3) Output projection: (128 x 1024) @ (1024 x 1024)^T + b -> out
    {
        dim3 grid(CDIM / GBN, M_ROWS / GBM);
        gemm_bias_kernel<<<grid, 256>>>(nullptr, W_proj, b_proj, out,
                                        M_ROWS, CDIM, CDIM, 2);
    }
}

// round 5
// speedup vs baseline: 1.2904x; 1.2904x over previous
#include <cuda_runtime.h>
#include <cuda_bf16.h>
#include <math.h>

// Problem constants
#define BATCH   16
#define HEADS   16
#define T_NEW   8
#define T_PAST  4096
#define T_FULL  4104
#define HD      64
#define CDIM    1024
#define M_ROWS  128          // B*T_new
#define QKV_N   3072

#define ATILE   128          // keys per tile in attention
#define NSPLIT  4            // KV splits (1024 past keys each; split 3 adds 8 new)
#define SPAD    132          // S_s row stride (conflict-free p reads)
#define VPAD    68           // v_s row stride (conflict-free float4 reads)

// Scratch (device globals; no allocations allowed)
__device__ float  g_qkv[M_ROWS * QKV_N];              // QKV projection output
__device__ float  g_y[M_ROWS * CDIM];                 // attention output
__device__ float  g_py[NSPLIT * 256 * T_NEW * HD];    // 2MB split partial y
__device__ float2 g_ml[NSPLIT * 256 * T_NEW];         // split partial (m,l)

// ---------------------------------------------------------------------------
// fp32 GEMM: C = A @ W^T + b. BM=32, BN=64, BK=16, 256 thr, 2x4 per thread.
// mode 1: C := g_qkv. mode 2: A := g_y.
// ---------------------------------------------------------------------------
#define GBM 32
#define GBN 64
#define GBK 16

__global__ void __launch_bounds__(256) gemm_bias_kernel(
    const float* __restrict__ Ap, const float* __restrict__ W,
    const float* __restrict__ bias, float* __restrict__ Cp,
    int M, int N, int K, int mode)
{
    const float* A = (mode == 2) ? g_y : Ap;
    float* C = (mode == 1) ? g_qkv : Cp;

    __shared__ float a_s[GBK][GBM + 2];
    __shared__ float b_s[GBK][GBN + 4];

    const int tid = threadIdx.x;
    const int m0 = blockIdx.y * GBM;
    const int n0 = blockIdx.x * GBN;

    const int tx = tid & 15;     // n sub (4 cols each)
    const int ty = tid >> 4;     // m sub (2 rows each)

    float acc[2][4];
#pragma unroll
    for (int i = 0; i < 2; i++)
#pragma unroll
        for (int j = 0; j < 4; j++) acc[i][j] = 0.f;

    for (int k0 = 0; k0 < K; k0 += GBK) {
        if (tid < 128) {   // A tile: 32x16 = 128 float4
            const int r = tid >> 2, c4 = tid & 3;
            const float4 v = *(const float4*)&A[(size_t)(m0 + r) * K + k0 + 4 * c4];
            a_s[4 * c4 + 0][r] = v.x;
            a_s[4 * c4 + 1][r] = v.y;
            a_s[4 * c4 + 2][r] = v.z;
            a_s[4 * c4 + 3][r] = v.w;
        }
        {   // B tile: 64x16 = 256 float4
            const int r = tid >> 2, c4 = tid & 3;
            const float4 v = *(const float4*)&W[(size_t)(n0 + r) * K + k0 + 4 * c4];
            b_s[4 * c4 + 0][r] = v.x;
            b_s[4 * c4 + 1][r] = v.y;
            b_s[4 * c4 + 2][r] = v.z;
            b_s[4 * c4 + 3][r] = v.w;
        }
        __syncthreads();

#pragma unroll
        for (int kk = 0; kk < GBK; kk++) {
            const float2 av = *(const float2*)&a_s[kk][ty * 2];
            const float4 bv = *(const float4*)&b_s[kk][tx * 4];
            acc[0][0] += av.x * bv.x; acc[0][1] += av.x * bv.y;
            acc[0][2] += av.x * bv.z; acc[0][3] += av.x * bv.w;
            acc[1][0] += av.y * bv.x; acc[1][1] += av.y * bv.y;
            acc[1][2] += av.y * bv.z; acc[1][3] += av.y * bv.w;
        }
        __syncthreads();
    }

    const float4 bb = *(const float4*)&bias[n0 + tx * 4];
#pragma unroll
    for (int i = 0; i < 2; i++) {
        const size_t row = (size_t)(m0 + ty * 2 + i);
        float4 o;
        o.x = acc[i][0] + bb.x; o.y = acc[i][1] + bb.y;
        o.z = acc[i][2] + bb.z; o.w = acc[i][3] + bb.w;
        *(float4*)&C[row * N + n0 + tx * 4] = o;
    }
}

// ---------------------------------------------------------------------------
// Fused attention + KV-cache copy, split-KV.
// Grid (256, 4): blockIdx.x = bh, blockIdx.y = split. 256 threads, 8 warps.
// Split s handles keys [s*1024, s*1024+1024); split 3 also the 8 new keys.
// Per tile (<=128 keys):
//   - thread pair (2r,2r+1) owns key row r, loads half-rows of K/V, writes
//     them to out_k/out_v (fused cache copy), computes partial scores for all
//     8 queries; pair-combine shfl is WARP-UNIFORM.
//   - warp w: online softmax for query w; writes p into S_s, factor into f_s.
//   - PV: warp w owns d in [8w,8w+8) for ALL queries; lane = (qi=lane&7,
//     jg=lane>>3); conflict-free padded-stride smem reads; acc[8] registers.
// End: shfl-reduce over jg, lanes 0..7 write partial y; lane 0 writes (m,l).
// Smem: 512 + 8*132 + 128*68 + 8 floats = ~41 KB static.
// ---------------------------------------------------------------------------
__global__ void __launch_bounds__(256) attn_fused_kernel(
    const float* __restrict__ past_k, const float* __restrict__ past_v,
    float* __restrict__ out_k, float* __restrict__ out_v)
{
    __shared__ float q_s[T_NEW * HD];
    __shared__ float S_s[T_NEW * SPAD];
    __shared__ float v_s[ATILE * VPAD];     // [j][d] stride VPAD
    __shared__ float f_s[T_NEW];

    const int bh = blockIdx.x;
    const int split = blockIdx.y;
    const int b = bh >> 4;
    const int h = bh & 15;
    const int tid = threadIdx.x;
    const int lane = tid & 31;
    const int w = tid >> 5;

    const int row  = tid >> 1;   // key row within tile
    const int half = tid & 1;    // half-row (32 dims)

    const int qi = lane & 7;     // PV: query owned by this lane
    const int jg = lane >> 3;    // PV: j subgroup

    // load q (scaled by 1/sqrt(hd) = 0.125)
    for (int idx = tid; idx < T_NEW * HD; idx += 256) {
        const int qq = idx >> 6, d = idx & 63;
        q_s[idx] = g_qkv[(size_t)(b * T_NEW + qq) * QKV_N + h * HD + d] * 0.125f;
    }
    __syncthreads();

    float m = -INFINITY, l = 0.f;
    float acc[8];
#pragma unroll
    for (int d = 0; d < 8; d++) acc[d] = 0.f;

    const float4* qs4 = (const float4*)q_s;
    const int tmax = (split == NSPLIT - 1) ? 9 : 8;

    for (int t = 0; t < tmax; t++) {
        const int nk = (t < 8) ? ATILE : T_NEW;
        const int kt = split * 1024 + t * ATILE + row;   // t==8 -> 4096+row
        const bool active = (row < nk);

        const float *kptr = nullptr, *vptr = nullptr;
        float *okp = nullptr, *ovp = nullptr;
        if (active) {
            if (kt < T_PAST) {
                kptr = past_k + ((size_t)bh * T_PAST + kt) * HD;
                vptr = past_v + ((size_t)bh * T_PAST + kt) * HD;
            } else {
                const int ni = kt - T_PAST;
                kptr = g_qkv + (size_t)(b * T_NEW + ni) * QKV_N + CDIM + h * HD;
                vptr = g_qkv + (size_t)(b * T_NEW + ni) * QKV_N + 2 * CDIM + h * HD;
            }
            okp = out_k + ((size_t)bh * T_FULL + kt) * HD;
            ovp = out_v + ((size_t)bh * T_FULL + kt) * HD;
        }

        // --- K: load half row, fused copy-out, partial scores ---
        float s[8];
#pragma unroll
        for (int q2 = 0; q2 < 8; q2++) s[q2] = 0.f;
        if (active) {
            const float4* k4 = (const float4*)(kptr) + half * 8;
            float4* ok4 = (float4*)(okp) + half * 8;
#pragma unroll
            for (int c = 0; c < 8; c++) {
                const float4 kv = k4[c];
                ok4[c] = kv;
#pragma unroll
                for (int q2 = 0; q2 < 8; q2++) {
                    const float4 qv = qs4[q2 * 16 + half * 8 + c];
                    s[q2] += qv.x * kv.x + qv.y * kv.y + qv.z * kv.z + qv.w * kv.w;
                }
            }
        }
        // pair-combine: WARP-UNIFORM
#pragma unroll
        for (int q2 = 0; q2 < 8; q2++)
            s[q2] += __shfl_xor_sync(0xffffffffu, s[q2], 1);

        // causal mask for the 8 new keys (only split 3 sees them)
        if (active && kt >= T_PAST) {
            const int ni = kt - T_PAST;
#pragma unroll
            for (int q2 = 0; q2 < 8; q2++)
                if (q2 < ni) s[q2] = -INFINITY;
        }
        if (half == 0) {
#pragma unroll
            for (int q2 = 0; q2 < 8; q2++)
                S_s[q2 * SPAD + row] = active ? s[q2] : -INFINITY;
        }

        // --- V: load half row, fused copy-out, STS.128 transposed-ish store ---
        if (active) {
            const float4* v4 = (const float4*)(vptr) + half * 8;
            float4* ov4 = (float4*)(ovp) + half * 8;
#pragma unroll
            for (int c = 0; c < 8; c++) {
                const float4 vv = v4[c];
                ov4[c] = vv;
                *(float4*)&v_s[row * VPAD + half * 32 + c * 4] = vv;
            }
        }
        __syncthreads();

        // --- online softmax: warp w owns query w ---
        float pr[4];
        float lmax = -INFINITY;
#pragma unroll
        for (int k = 0; k < 4; k++) {
            pr[k] = S_s[w * SPAD + lane + 32 * k];
            lmax = fmaxf(lmax, pr[k]);
        }
#pragma unroll
        for (int off = 16; off; off >>= 1)
            lmax = fmaxf(lmax, __shfl_xor_sync(0xffffffffu, lmax, off));
        const float m_new = fmaxf(m, lmax);
        const float factor = __expf(m - m_new);
        float psum = 0.f;
#pragma unroll
        for (int k = 0; k < 4; k++) {
            const float e = __expf(pr[k] - m_new);
            psum += e;
            S_s[w * SPAD + lane + 32 * k] = e;
        }
#pragma unroll
        for (int off = 16; off; off >>= 1)
            psum += __shfl_xor_sync(0xffffffffu, psum, off);
        l = l * factor + psum;
        m = m_new;
        if (lane == 0) f_s[w] = factor;
        __syncthreads();   // PV reads S_s/f_s written by ALL warps

        // --- PV: warp w covers d in [8w, 8w+8), lane = (qi, jg) ---
        {
            const float fct = f_s[qi];
#pragma unroll
            for (int d = 0; d < 8; d++) acc[d] *= fct;
            const float* vrow = v_s + w * 8;
#pragma unroll 4
            for (int jb = 0; jb < 32; jb++) {
                const int j = jb * 4 + jg;
                const float p = S_s[qi * SPAD + j];
                const float4 va = *(const float4*)&vrow[j * VPAD];
                const float4 vb = *(const float4*)&vrow[j * VPAD + 4];
                acc[0] += p * va.x; acc[1] += p * va.y;
                acc[2] += p * va.z; acc[3] += p * va.w;
                acc[4] += p * vb.x; acc[5] += p * vb.y;
                acc[6] += p * vb.z; acc[7] += p * vb.w;
            }
        }
        __syncthreads();   // protect S_s / v_s before next tile
    }

    // reduce over jg (lanes qi, qi+8, qi+16, qi+24) — warp-uniform shfls
#pragma unroll
    for (int d = 0; d < 8; d++) {
        acc[d] += __shfl_xor_sync(0xffffffffu, acc[d], 8);
        acc[d] += __shfl_xor_sync(0xffffffffu, acc[d], 16);
    }
    if (lane < 8) {
        const size_t base = ((size_t)(split * 256 + bh) * T_NEW + lane) * HD + w * 8;
        *(float4*)&g_py[base]     = make_float4(acc[0], acc[1], acc[2], acc[3]);
        *(float4*)&g_py[base + 4] = make_float4(acc[4], acc[5], acc[6], acc[7]);
    }
    if (lane == 0)
        g_ml[(split * 256 + bh) * T_NEW + w] = make_float2(m, l);
}

// ---------------------------------------------------------------------------
// Combine split partials -> g_y. Grid 256 (bh), 256 threads.
// thread: qi = tid>>5, dd = (tid&31)*2 (float2 of d).
// ---------------------------------------------------------------------------
__global__ void __launch_bounds__(256) combine_kernel()
{
    const int bh = blockIdx.x;
    const int b = bh >> 4;
    const int h = bh & 15;
    const int tid = threadIdx.x;
    const int qi = tid >> 5;
    const int dd = (tid & 31) * 2;

    float2 ml[NSPLIT];
    float M = -INFINITY;
#pragma unroll
    for (int s = 0; s < NSPLIT; s++) {
        ml[s] = g_ml[(s * 256 + bh) * T_NEW + qi];
        M = fmaxf(M, ml[s].x);
    }
    float lt = 0.f, y0 = 0.f, y1 = 0.f;
#pragma unroll
    for (int s = 0; s < NSPLIT; s++) {
        const float wt = __expf(ml[s].x - M);
        lt += ml[s].y * wt;
        const float2 yv = *(const float2*)
            &g_py[((size_t)(s * 256 + bh) * T_NEW + qi) * HD + dd];
        y0 += yv.x * wt;
        y1 += yv.y * wt;
    }
    const float inv = 1.f / lt;
    *(float2*)&g_y[(size_t)(b * T_NEW + qi) * CDIM + h * HD + dd] =
        make_float2(y0 * inv, y1 * inv);
}

// ---------------------------------------------------------------------------
// Launcher — ONLY kernel launches.
// Inputs: 0:x 1:past_k 2:past_v 3:W_attn 4:b_attn 5:W_proj 6:b_proj
// Output layout: [ out (128*1024) | k (256*4104*64) | v (256*4104*64) ]
// ---------------------------------------------------------------------------
extern "C" void kernel_launch(void* const* d_in, const int* in_sizes, int n_in,
                              void* d_out, int out_size)
{
    const float* x      = (const float*)d_in[0];
    const float* past_k = (const float*)d_in[1];
    const float* past_v = (const float*)d_in[2];
    const float* W_attn = (const float*)d_in[3];
    const float* b_attn = (const float*)d_in[4];
    const float* W_proj = (const float*)d_in[5];
    const float* b_proj = (const float*)d_in[6];

    float* out   = (float*)d_out;
    float* out_k = out + (size_t)M_ROWS * CDIM;
    float* out_v = out_k + (size_t)BATCH * HEADS * T_FULL * HD;

    // 1) QKV projection -> g_qkv
    {
        dim3 grid(QKV_N / GBN, M_ROWS / GBM);   // (48, 4) = 192 blocks
        gemm_bias_kernel<<<grid, 256>>>(x, W_attn, b_attn, nullptr,
                                        M_ROWS, QKV_N, CDIM, 1);
    }

    // 2) Fused attention + KV-cache copy (split-KV)
    {
        dim3 grid(BATCH * HEADS, NSPLIT);       // (256, 4) = 1024 blocks
        attn_fused_kernel<<<grid, 256>>>(past_k, past_v, out_k, out_v);
    }

    // 3) Combine split partials -> g_y
    combine_kernel<<<BATCH * HEADS, 256>>>();

    // 4) Output projection -> out
    {
        dim3 grid(CDIM / GBN, M_ROWS / GBM);    // (16, 4) = 64 blocks
        gemm_bias_kernel<<<grid, 256>>>(nullptr, W_proj, b_proj, out,
                                        M_ROWS, CDIM, CDIM, 2);
    }
}

// round 6
// speedup vs baseline: 1.9661x; 1.5236x over previous
#include <cuda_runtime.h>
#include <cuda_bf16.h>
#include <math.h>

// Problem constants
#define BATCH   16
#define HEADS   16
#define T_NEW   8
#define T_PAST  4096
#define T_FULL  4104
#define HD      64
#define CDIM    1024
#define M_ROWS  128          // B*T_new
#define QKV_N   3072

#define ATILE   128          // keys per tile
#define NSPLIT  4            // KV splits
#define SPAD    132          // S_s row stride
#define VPAD    72           // v_s row stride (halves at +0 / +36)

// Scratch (device globals; no allocations allowed)
__device__ float  g_qkv[M_ROWS * QKV_N];
__device__ float  g_y[M_ROWS * CDIM];
__device__ float  g_py[NSPLIT * 256 * T_NEW * HD];
__device__ float2 g_ml[NSPLIT * 256 * T_NEW];

// ---------------------------------------------------------------------------
// fp32 GEMM: C = A @ W^T + b. Template BM/BN/NT; BK=16; 1 row x 4 cols/thread.
// mode 1: C := g_qkv. mode 2: A := g_y.
// ---------------------------------------------------------------------------
template<int BM, int BN, int NT>
__global__ void __launch_bounds__(NT) gemm_bias_t(
    const float* __restrict__ Ap, const float* __restrict__ W,
    const float* __restrict__ bias, float* __restrict__ Cp,
    int M, int N, int K, int mode)
{
    const float* A = (mode == 2) ? g_y : Ap;
    float* C = (mode == 1) ? g_qkv : Cp;

    __shared__ float a_s[16][BM + 4];
    __shared__ float b_s[16][BN + 4];

    const int tid = threadIdx.x;
    const int m0 = blockIdx.y * BM;
    const int n0 = blockIdx.x * BN;
    constexpr int G = BN / 4;
    const int tx = tid % G;
    const int ty = tid / G;

    float acc[4] = {0.f, 0.f, 0.f, 0.f};

    for (int k0 = 0; k0 < K; k0 += 16) {
        for (int i = tid; i < BM * 4; i += NT) {
            const int r = i >> 2, c4 = i & 3;
            const float4 v = *(const float4*)&A[(size_t)(m0 + r) * K + k0 + 4 * c4];
            a_s[4 * c4 + 0][r] = v.x; a_s[4 * c4 + 1][r] = v.y;
            a_s[4 * c4 + 2][r] = v.z; a_s[4 * c4 + 3][r] = v.w;
        }
        for (int i = tid; i < BN * 4; i += NT) {
            const int r = i >> 2, c4 = i & 3;
            const float4 v = *(const float4*)&W[(size_t)(n0 + r) * K + k0 + 4 * c4];
            b_s[4 * c4 + 0][r] = v.x; b_s[4 * c4 + 1][r] = v.y;
            b_s[4 * c4 + 2][r] = v.z; b_s[4 * c4 + 3][r] = v.w;
        }
        __syncthreads();
#pragma unroll
        for (int kk = 0; kk < 16; kk++) {
            const float a = a_s[kk][ty];
            const float4 bv = *(const float4*)&b_s[kk][tx * 4];
            acc[0] += a * bv.x; acc[1] += a * bv.y;
            acc[2] += a * bv.z; acc[3] += a * bv.w;
        }
        __syncthreads();
    }
    const float4 bb = *(const float4*)&bias[n0 + tx * 4];
    const float4 o = make_float4(acc[0] + bb.x, acc[1] + bb.y,
                                 acc[2] + bb.z, acc[3] + bb.w);
    *(float4*)&C[(size_t)(m0 + ty) * N + n0 + tx * 4] = o;
}

// ---------------------------------------------------------------------------
// Fused attention + KV-cache copy, split-KV, fully coalesced global access.
// Grid (256, 4). 256 threads, 8 warps. Warp w owns rows [16w, 16w+16) of each
// 128-key tile; instruction i covers rows 16w+2i{+0,1}: lane = 16B chunk ->
// every LDG/STG.128 is 512B contiguous. Cache copy = register passthrough.
// Scores: per-lane 4-dim partials for all 8 queries, folded over the 16
// dim-lanes by a 15-shfl butterfly; lane ends with qi = lane&7.
// PV: warp w owns dims [8w,8w+8) for all queries; lane=(qi=lane&7, jg=lane>>3).
// ---------------------------------------------------------------------------
__global__ void __launch_bounds__(256, 2) attn_fused_kernel(
    const float* __restrict__ past_k, const float* __restrict__ past_v,
    float* __restrict__ out_k, float* __restrict__ out_v)
{
    __shared__ float q_s[T_NEW * HD];
    __shared__ float S_s[T_NEW * SPAD];
    __shared__ float v_s[ATILE * VPAD];   // row r: dims 0-31 at +0, 32-63 at +36
    __shared__ float f_s[T_NEW];

    const int bh = blockIdx.x;
    const int split = blockIdx.y;
    const int b = bh >> 4;
    const int h = bh & 15;
    const int tid = threadIdx.x;
    const int lane = tid & 31;
    const int w = tid >> 5;

    const int dg = lane & 15;    // 16B dim-chunk (dims 4dg..4dg+3)
    const int rh = lane >> 4;    // row half within instruction

    const int pqi = lane & 7;    // PV: query owned by this lane
    const int jg  = lane >> 3;   // PV: j subgroup
    const int voff = w * 8 + ((w >= 4) ? 4 : 0);

    // stage q to smem, then per-lane regs (dims 4dg..4dg+3 of each query)
    for (int idx = tid; idx < T_NEW * HD; idx += 256) {
        const int qq = idx >> 6, d = idx & 63;
        q_s[idx] = g_qkv[(size_t)(b * T_NEW + qq) * QKV_N + h * HD + d] * 0.125f;
    }
    __syncthreads();
    float4 qr[8];
#pragma unroll
    for (int qi = 0; qi < 8; qi++)
        qr[qi] = *(const float4*)&q_s[qi * HD + 4 * dg];

    float m = -INFINITY, l = 0.f;
    float acc[8];
#pragma unroll
    for (int d = 0; d < 8; d++) acc[d] = 0.f;

    const int tmax = (split == NSPLIT - 1) ? 9 : 8;

    for (int t = 0; t < tmax; t++) {
        const int nk = (t < 8) ? ATILE : T_NEW;
        const int tilebase = split * 1024 + t * ATILE;

        // --- load K and V rows (coalesced 512B per warp instruction) ---
        float4 kr[8], vr[8];
#pragma unroll
        for (int i = 0; i < 8; i++) {
            const int r = 16 * w + 2 * i + rh;
            const int kt = tilebase + r;
            if (r < nk) {
                const float* ks;
                const float* vs;
                if (kt < T_PAST) {
                    ks = past_k + ((size_t)bh * T_PAST + kt) * HD + 4 * dg;
                    vs = past_v + ((size_t)bh * T_PAST + kt) * HD + 4 * dg;
                } else {
                    const size_t nb = (size_t)(b * T_NEW + (kt - T_PAST)) * QKV_N + h * HD + 4 * dg;
                    ks = g_qkv + nb + CDIM;
                    vs = g_qkv + nb + 2 * CDIM;
                }
                kr[i] = *(const float4*)ks;
                vr[i] = *(const float4*)vs;
            } else {
                kr[i] = make_float4(0.f, 0.f, 0.f, 0.f);
                vr[i] = make_float4(0.f, 0.f, 0.f, 0.f);
            }
        }
        // --- fused cache copy-out (register passthrough, coalesced) ---
#pragma unroll
        for (int i = 0; i < 8; i++) {
            const int r = 16 * w + 2 * i + rh;
            const int kt = tilebase + r;
            if (r < nk) {
                *(float4*)&out_k[((size_t)bh * T_FULL + kt) * HD + 4 * dg] = kr[i];
                *(float4*)&out_v[((size_t)bh * T_FULL + kt) * HD + 4 * dg] = vr[i];
                // V into smem (conflict-free: stride 72, halves at +0/+36)
                *(float4*)&v_s[r * VPAD + 4 * dg + ((dg >= 8) ? 4 : 0)] = vr[i];
            }
        }

        // --- scores: butterfly-fold partials over the 16 dim-lanes ---
#pragma unroll
        for (int i = 0; i < 8; i++) {
            float p[8];
#pragma unroll
            for (int qi = 0; qi < 8; qi++)
                p[qi] = qr[qi].x * kr[i].x + qr[qi].y * kr[i].y
                      + qr[qi].z * kr[i].z + qr[qi].w * kr[i].w;
            // sum lanes l and l^8 (dim halves)
#pragma unroll
            for (int qi = 0; qi < 8; qi++)
                p[qi] += __shfl_xor_sync(0xffffffffu, p[qi], 8);
            // fold 8 -> 4 (xor 4): keep qi-half matching lane bit2
#pragma unroll
            for (int q = 0; q < 4; q++) {
                const float send = (lane & 4) ? p[q] : p[q + 4];
                const float got = __shfl_xor_sync(0xffffffffu, send, 4);
                p[q] = ((lane & 4) ? p[q + 4] : p[q]) + got;
            }
#pragma unroll
            for (int q = 0; q < 2; q++) {
                const float send = (lane & 2) ? p[q] : p[q + 2];
                const float got = __shfl_xor_sync(0xffffffffu, send, 2);
                p[q] = ((lane & 2) ? p[q + 2] : p[q]) + got;
            }
            {
                const float send = (lane & 1) ? p[0] : p[1];
                const float got = __shfl_xor_sync(0xffffffffu, send, 1);
                p[0] = ((lane & 1) ? p[1] : p[0]) + got;
            }
            // lane holds s(row = 16w+2i+(lane>>4), qi = lane&7)
            if ((lane & 8) == 0) {
                const int r = 16 * w + 2 * i + (lane >> 4);
                const int kt2 = tilebase + r;
                float sv = p[0];
                if (r >= nk) sv = -INFINITY;
                else if (kt2 >= T_PAST && pqi < (kt2 - T_PAST)) sv = -INFINITY;
                S_s[pqi * SPAD + r] = sv;
            }
        }
        __syncthreads();

        // --- online softmax: warp w owns query w ---
        float pr[4];
        float lmax = -INFINITY;
#pragma unroll
        for (int k = 0; k < 4; k++) {
            pr[k] = S_s[w * SPAD + lane + 32 * k];
            lmax = fmaxf(lmax, pr[k]);
        }
#pragma unroll
        for (int off = 16; off; off >>= 1)
            lmax = fmaxf(lmax, __shfl_xor_sync(0xffffffffu, lmax, off));
        const float m_new = fmaxf(m, lmax);
        const float factor = __expf(m - m_new);
        float psum = 0.f;
#pragma unroll
        for (int k = 0; k < 4; k++) {
            const float e = __expf(pr[k] - m_new);
            psum += e;
            S_s[w * SPAD + lane + 32 * k] = e;
        }
#pragma unroll
        for (int off = 16; off; off >>= 1)
            psum += __shfl_xor_sync(0xffffffffu, psum, off);
        l = l * factor + psum;
        m = m_new;
        if (lane == 0) f_s[w] = factor;
        __syncthreads();

        // --- PV: warp w covers dims [8w,8w+8); lane = (pqi, jg) ---
        {
            const float fct = f_s[pqi];
#pragma unroll
            for (int d = 0; d < 8; d++) acc[d] *= fct;
            const float* vrow = v_s + voff;
#pragma unroll 4
            for (int jb = 0; jb < 32; jb++) {
                const int j = jb * 4 + jg;
                const float p = S_s[pqi * SPAD + j];
                const float4 va = *(const float4*)&vrow[j * VPAD];
                const float4 vb = *(const float4*)&vrow[j * VPAD + 4];
                acc[0] += p * va.x; acc[1] += p * va.y;
                acc[2] += p * va.z; acc[3] += p * va.w;
                acc[4] += p * vb.x; acc[5] += p * vb.y;
                acc[6] += p * vb.z; acc[7] += p * vb.w;
            }
        }
        __syncthreads();
    }

    // reduce over jg (xor 8, 16) — warp-uniform
#pragma unroll
    for (int d = 0; d < 8; d++) {
        acc[d] += __shfl_xor_sync(0xffffffffu, acc[d], 8);
        acc[d] += __shfl_xor_sync(0xffffffffu, acc[d], 16);
    }
    if (lane < 8) {
        const size_t base = ((size_t)(split * 256 + bh) * T_NEW + lane) * HD + w * 8;
        *(float4*)&g_py[base]     = make_float4(acc[0], acc[1], acc[2], acc[3]);
        *(float4*)&g_py[base + 4] = make_float4(acc[4], acc[5], acc[6], acc[7]);
    }
    if (lane == 0)
        g_ml[(split * 256 + bh) * T_NEW + w] = make_float2(m, l);
}

// ---------------------------------------------------------------------------
// Combine split partials -> g_y. Grid 256 (bh), 256 threads.
// ---------------------------------------------------------------------------
__global__ void __launch_bounds__(256) combine_kernel()
{
    const int bh = blockIdx.x;
    const int b = bh >> 4;
    const int h = bh & 15;
    const int tid = threadIdx.x;
    const int qi = tid >> 5;
    const int dd = (tid & 31) * 2;

    float2 ml[NSPLIT];
    float M = -INFINITY;
#pragma unroll
    for (int s = 0; s < NSPLIT; s++) {
        ml[s] = g_ml[(s * 256 + bh) * T_NEW + qi];
        M = fmaxf(M, ml[s].x);
    }
    float lt = 0.f, y0 = 0.f, y1 = 0.f;
#pragma unroll
    for (int s = 0; s < NSPLIT; s++) {
        const float wt = __expf(ml[s].x - M);
        lt += ml[s].y * wt;
        const float2 yv = *(const float2*)
            &g_py[((size_t)(s * 256 + bh) * T_NEW + qi) * HD + dd];
        y0 += yv.x * wt;
        y1 += yv.y * wt;
    }
    const float inv = 1.f / lt;
    *(float2*)&g_y[(size_t)(b * T_NEW + qi) * CDIM + h * HD + dd] =
        make_float2(y0 * inv, y1 * inv);
}

// ---------------------------------------------------------------------------
// Launcher — ONLY kernel launches.
// Output layout: [ out (128*1024) | k (256*4104*64) | v (256*4104*64) ]
// ---------------------------------------------------------------------------
extern "C" void kernel_launch(void* const* d_in, const int* in_sizes, int n_in,
                              void* d_out, int out_size)
{
    const float* x      = (const float*)d_in[0];
    const float* past_k = (const float*)d_in[1];
    const float* past_v = (const float*)d_in[2];
    const float* W_attn = (const float*)d_in[3];
    const float* b_attn = (const float*)d_in[4];
    const float* W_proj = (const float*)d_in[5];
    const float* b_proj = (const float*)d_in[6];

    float* out   = (float*)d_out;
    float* out_k = out + (size_t)M_ROWS * CDIM;
    float* out_v = out_k + (size_t)BATCH * HEADS * T_FULL * HD;

    // 1) QKV projection -> g_qkv  (384 blocks)
    {
        dim3 grid(QKV_N / 64, M_ROWS / 16);
        gemm_bias_t<16, 64, 256><<<grid, 256>>>(x, W_attn, b_attn, nullptr,
                                                M_ROWS, QKV_N, CDIM, 1);
    }

    // 2) Fused attention + KV-cache copy (split-KV, 1024 blocks)
    {
        dim3 grid(BATCH * HEADS, NSPLIT);
        attn_fused_kernel<<<grid, 256>>>(past_k, past_v, out_k, out_v);
    }

    // 3) Combine split partials -> g_y
    combine_kernel<<<BATCH * HEADS, 256>>>();

    // 4) Output projection -> out  (256 blocks)
    {
        dim3 grid(CDIM / 32, M_ROWS / 16);
        gemm_bias_t<16, 32, 128><<<grid, 128>>>(nullptr, W_proj, b_proj, out,
                                                M_ROWS, CDIM, CDIM, 2);
    }
}